// round 5
// baseline (speedup 1.0000x reference)
#include <cuda_runtime.h>
#include <cstdint>

// Problem constants
#define BB    128
#define LL    9
#define KK    3
#define PP    1680
#define CIN   256
#define COUT  256
#define ZR    1152
#define ZC    768
#define KSPLIT 4

// Scratch (device globals: allocation-free)
__device__ float g_Z[KSPLIT * ZR * ZC];   // 13.6 MB, 4 K-partials
__device__ int   g_codes[PP];

// ---------------------------------------------------------------------------
// GEMM partial: Z[ks][r,j] = sum_{c in ks*64..+64} X[r,c] * Wm[j,c]
// 64x64 tile, one 64-wide K chunk per block, transposed smem, 4x4 reg tile,
// register prefetch. grid = (9 row-blocks of this half, 12, KSPLIT).
// Blocks (by==0, bz==0) of the first half also decode permutation codes.
// ---------------------------------------------------------------------------
__global__ void __launch_bounds__(256) gemm_z(const float* __restrict__ X,
                                              const float* __restrict__ Wm,
                                              const float* __restrict__ M,
                                              int row_base) {
    __shared__ float sXt[64][68];
    __shared__ float sWt[64][68];

    const int t  = threadIdx.x;
    const int rb = row_base + blockIdx.x * 64;
    const int jb = blockIdx.y * 64;
    const int kc = blockIdx.z * 64;

    // fused code decode (first half only, 9 blocks x 256 threads >= 1680)
    if (M != nullptr && blockIdx.y == 0 && blockIdx.z == 0) {
        int p = blockIdx.x * 256 + t;
        if (p < PP) {
            const int PL = PP * LL;
            int c[3] = {0, 0, 0};
            const int w3[3] = {1, 3, 9};
#pragma unroll
            for (int l = 0; l < LL; l++) {
                float m1 = M[PL + p * LL + l];
                float m2 = M[2 * PL + p * LL + l];
                int a = (m1 > 0.5f) ? 1 : ((m2 > 0.5f) ? 2 : 0);
                c[l / 3] += a * w3[l % 3];
            }
            g_codes[p] = c[0] | (c[1] << 8) | (c[2] << 16);
        }
    }

    const int c4 = t & 15;
    const int rr = t >> 4;

    float acc[4][4];
#pragma unroll
    for (int i = 0; i < 4; i++)
#pragma unroll
        for (int j = 0; j < 4; j++) acc[i][j] = 0.0f;

    const int row0 = (t >> 4) * 4;
    const int col0 = (t & 15) * 4;

#pragma unroll
    for (int i = 0; i < 4; i++) {
        int r = rr + i * 16;
        float4 v = *(const float4*)&X[(rb + r) * CIN + kc + c4 * 4];
        sXt[c4 * 4 + 0][r] = v.x;
        sXt[c4 * 4 + 1][r] = v.y;
        sXt[c4 * 4 + 2][r] = v.z;
        sXt[c4 * 4 + 3][r] = v.w;
        float4 w = *(const float4*)&Wm[(jb + r) * CIN + kc + c4 * 4];
        sWt[c4 * 4 + 0][r] = w.x;
        sWt[c4 * 4 + 1][r] = w.y;
        sWt[c4 * 4 + 2][r] = w.z;
        sWt[c4 * 4 + 3][r] = w.w;
    }
    __syncthreads();

    float4 xa = *(const float4*)&sXt[0][row0];
    float4 wb = *(const float4*)&sWt[0][col0];
#pragma unroll
    for (int c = 0; c < 64; c++) {
        float4 xc = xa, wc = wb;
        if (c < 63) {
            xa = *(const float4*)&sXt[c + 1][row0];
            wb = *(const float4*)&sWt[c + 1][col0];
        }
        acc[0][0] += xc.x * wc.x; acc[0][1] += xc.x * wc.y;
        acc[0][2] += xc.x * wc.z; acc[0][3] += xc.x * wc.w;
        acc[1][0] += xc.y * wc.x; acc[1][1] += xc.y * wc.y;
        acc[1][2] += xc.y * wc.z; acc[1][3] += xc.y * wc.w;
        acc[2][0] += xc.z * wc.x; acc[2][1] += xc.z * wc.y;
        acc[2][2] += xc.z * wc.z; acc[2][3] += xc.z * wc.w;
        acc[3][0] += xc.w * wc.x; acc[3][1] += xc.w * wc.y;
        acc[3][2] += xc.w * wc.z; acc[3][3] += xc.w * wc.w;
    }

    float4* Z4 = (float4*)(g_Z + blockIdx.z * (ZR * ZC));
#pragma unroll
    for (int i = 0; i < 4; i++) {
        float4 v = make_float4(acc[i][0], acc[i][1], acc[i][2], acc[i][3]);
        Z4[(rb + row0 + i) * (ZC / 4) + (jb + col0) / 4] = v;
    }
}

// ---------------------------------------------------------------------------
// Combine: stage summed Z-slice (27 vrows x 32 f4) into smem, build the
// 81-entry partial-sum table in smem, then stream outputs.
// grid = (5 p-chunks, 2 channel halves, 64 b of this half), 256 threads.
// ---------------------------------------------------------------------------
#define PCHUNK 336
#define NCHUNK 5

__global__ void __launch_bounds__(256) perm_combine(float* __restrict__ out,
                                                    int b_base) {
    __shared__ float4 sT4[81 * 32];
    __shared__ float4 sZ[27 * 32];
    __shared__ int sCodes[PCHUNK];

    const int t     = threadIdx.x;
    const int chunk = blockIdx.x;
    const int h     = blockIdx.y;
    const int b     = b_base + blockIdx.z;
    const int pbase = chunk * PCHUNK;

    // ---- stage summed Z slice: vr = l*3 + k ----
    const float4* Z0 = (const float4*)g_Z;
    const int pstride = (ZR * ZC) / 4;
    for (int i = t; i < 27 * 32; i += 256) {
        int vr = i >> 5;
        int o4 = i & 31;
        int l = vr / 3, k = vr - 3 * l;
        int idx = (b * LL + l) * (ZC / 4) + k * (COUT / 4) + h * 32 + o4;
        float4 a = Z0[idx];
        float4 bb = Z0[idx + pstride];
        float4 c = Z0[idx + 2 * pstride];
        float4 d = Z0[idx + 3 * pstride];
        float4 s;
        s.x = (a.x + bb.x) + (c.x + d.x);
        s.y = (a.y + bb.y) + (c.y + d.y);
        s.z = (a.z + bb.z) + (c.z + d.z);
        s.w = (a.w + bb.w) + (c.w + d.w);
        sZ[i] = s;
    }
    for (int i = t; i < PCHUNK; i += 256) sCodes[i] = g_codes[pbase + i];
    __syncthreads();

    // ---- build 81-entry table from smem ----
    for (int i = t; i < 81 * 32; i += 256) {
        int cc = i >> 5;
        int o4 = i & 31;
        int g  = cc / 27;
        int c  = cc - g * 27;
        int d0 = c % 3, d1 = (c / 3) % 3, d2 = c / 9;
        float4 v0 = sZ[(9 * g + 0 + d0) * 32 + o4];
        float4 v1 = sZ[(9 * g + 3 + d1) * 32 + o4];
        float4 v2 = sZ[(9 * g + 6 + d2) * 32 + o4];
        float4 s;
        s.x = v0.x + v1.x + v2.x;
        s.y = v0.y + v1.y + v2.y;
        s.z = v0.z + v1.z + v2.z;
        s.w = v0.w + v1.w + v2.w;
        sT4[i] = s;
    }
    __syncthreads();

    // ---- combine + stream out ----
    const int o4 = t & 31;
    const int pw = t >> 5;
    float4* out4 = (float4*)out;
    const int obase = (b * PP + pbase) * (COUT / 4) + h * 32 + o4;

#pragma unroll 2
    for (int it = 0; it < PCHUNK / 8; it++) {
        int po   = it * 8 + pw;
        int code = sCodes[po];
        int c0 = code & 0xFF;
        int c1 = (code >> 8) & 0xFF;
        int c2 = (code >> 16) & 0xFF;
        float4 a  = sT4[c0 * 32 + o4];
        float4 bb = sT4[(27 + c1) * 32 + o4];
        float4 cv = sT4[(54 + c2) * 32 + o4];
        float4 r;
        r.x = a.x + bb.x + cv.x;
        r.y = a.y + bb.y + cv.y;
        r.z = a.z + bb.z + cv.z;
        r.w = a.w + bb.w + cv.w;
        __stcs(&out4[obase + po * (COUT / 4)], r);
    }
}

// ---------------------------------------------------------------------------
extern "C" void kernel_launch(void* const* d_in, const int* in_sizes, int n_in,
                              void* d_out, int out_size) {
    (void)in_sizes; (void)n_in; (void)out_size;
    const float* x = (const float*)d_in[0];  // (128, 9, 256)
    const float* W = (const float*)d_in[1];  // (3, 256, 256)
    const float* M = (const float*)d_in[2];  // (3, 1680, 9)
    float* out = (float*)d_out;              // (128, 1680, 256)

    // one-time aux stream/events (created on the uncaptured correctness call)
    static cudaStream_t s2 = nullptr;
    static cudaEvent_t eFork = nullptr, eJoin = nullptr;
    if (s2 == nullptr) {
        cudaStreamCreateWithFlags(&s2, cudaStreamNonBlocking);
        cudaEventCreateWithFlags(&eFork, cudaEventDisableTiming);
        cudaEventCreateWithFlags(&eJoin, cudaEventDisableTiming);
    }

    // half 1: rows 0..575 (b 0..63), also decodes codes
    gemm_z<<<dim3(9, 12, KSPLIT), 256>>>(x, W, M, 0);
    cudaEventRecord(eFork, 0);
    cudaStreamWaitEvent(s2, eFork, 0);
    perm_combine<<<dim3(NCHUNK, 2, 64), 256, 0, s2>>>(out, 0);

    // half 2 on main stream, overlapping combine of half 1
    gemm_z<<<dim3(9, 12, KSPLIT), 256>>>(x, W, nullptr, 576);
    perm_combine<<<dim3(NCHUNK, 2, 64), 256>>>(out, 64);

    cudaEventRecord(eJoin, s2);
    cudaStreamWaitEvent(0, eJoin, 0);
}